// round 1
// baseline (speedup 1.0000x reference)
#include <cuda_runtime.h>
#include <cstdint>

#define TOK   2048
#define DIMSZ 1024
#define HID   2048
#define NE    8
#define NSLOT (2 * TOK)

// Scratch (allocation-free: __device__ globals)
__device__ float g_w[NSLOT];                       // combine weights per slot
__device__ int   g_cnt[NE];                        // tokens per expert
__device__ int   g_list[NE * TOK];                 // slot ids per expert
__device__ float g_h2[(size_t)NSLOT * HID];        // relu(x Wfc)^2, 32 MB
__device__ float g_y [(size_t)NSLOT * DIMSZ];      // per-slot proj output, 16 MB

// ---------------------------------------------------------------------------
__global__ void k_zero_counts() {
    if (threadIdx.x < NE) g_cnt[threadIdx.x] = 0;
}

// ---------------------------------------------------------------------------
// Router: one warp per token. logits -> softmax -> top2 -> renormalize (+1e-8)
__global__ void k_router(const float* __restrict__ x, const float* __restrict__ Wr) {
    int warp = threadIdx.x >> 5;
    int lane = threadIdx.x & 31;
    int t = blockIdx.x * 8 + warp;

    float acc[NE];
#pragma unroll
    for (int e = 0; e < NE; ++e) acc[e] = 0.f;

    const float* xr = x + (size_t)t * DIMSZ;
    for (int i = lane; i < DIMSZ; i += 32) {
        float xv = xr[i];
#pragma unroll
        for (int e = 0; e < NE; ++e) acc[e] = fmaf(xv, Wr[e * DIMSZ + i], acc[e]);
    }
#pragma unroll
    for (int e = 0; e < NE; ++e) {
#pragma unroll
        for (int o = 16; o > 0; o >>= 1)
            acc[e] += __shfl_xor_sync(0xffffffffu, acc[e], o);
    }
    if (lane == 0) {
        float m = acc[0];
#pragma unroll
        for (int e = 1; e < NE; ++e) m = fmaxf(m, acc[e]);
        float p[NE]; float Z = 0.f;
#pragma unroll
        for (int e = 0; e < NE; ++e) { p[e] = expf(acc[e] - m); Z += p[e]; }
        float invZ = 1.f / Z;
#pragma unroll
        for (int e = 0; e < NE; ++e) p[e] *= invZ;

        int e0 = 0;
#pragma unroll
        for (int e = 1; e < NE; ++e) if (p[e] > p[e0]) e0 = e;
        int e1 = (e0 == 0) ? 1 : 0;
#pragma unroll
        for (int e = 0; e < NE; ++e) { if (e != e0 && p[e] > p[e1]) e1 = e; }

        float s = p[e0] + p[e1] + 1e-8f;
        g_w[2 * t]     = p[e0] / s;
        g_w[2 * t + 1] = p[e1] / s;
        int q0 = atomicAdd(&g_cnt[e0], 1); g_list[e0 * TOK + q0] = 2 * t;
        int q1 = atomicAdd(&g_cnt[e1], 1); g_list[e1 * TOK + q1] = 2 * t + 1;
    }
}

// ---------------------------------------------------------------------------
// Grouped GEMM: C[slot, n] = sum_k A[row(slot), k] * W[e, n, k]
// 128x128 block tile, 16-wide k slab, double-buffered smem, 8x8/thread.
// Inner product via packed fp32x2 FFMA2 (2 MACs/instr).
// PHASE 1: A = x (row = slot>>1), C = g_h2, relu^2 epilogue
// PHASE 2: A = g_h2 (row = slot),  C = g_y
template<int KDIM, int NDIM, bool RELU2, int SHIFT, int PHASE>
__global__ void __launch_bounds__(256, 1)
k_gemm(const float* __restrict__ Ain, const float* __restrict__ Wall) {
    const float* Abase = (PHASE == 1) ? Ain : (const float*)g_h2;
    float*       Cbase = (PHASE == 1) ? (float*)g_h2 : (float*)g_y;

    int e   = blockIdx.z;
    int cnt = g_cnt[e];
    int m0  = blockIdx.y * 128;
    if (m0 >= cnt) return;                 // uniform early exit (before barriers)
    int n0  = blockIdx.x * 128;
    const float* W = Wall + (size_t)e * NDIM * KDIM;

    __shared__ __align__(16) float As[2][16][132];
    __shared__ __align__(16) float Bs[2][16][132];
    __shared__ int s_slot[128];
    __shared__ int s_aoff[128];

    int tid = threadIdx.x;
    if (tid < 128) {
        int idx = m0 + tid;
        int sl  = g_list[e * TOK + ((idx < cnt) ? idx : m0)];
        s_slot[tid] = (idx < cnt) ? sl : -1;
        s_aoff[tid] = (sl >> SHIFT) * KDIM;
    }
    __syncthreads();

    // Loader mapping: 256 threads -> rows lr and lr+64, k-quad lk
    int lr = tid >> 2;
    int lk = (tid & 3) << 2;
    const float* ap0 = Abase + s_aoff[lr]      + lk;
    const float* ap1 = Abase + s_aoff[lr + 64] + lk;
    const float* wp0 = W + (size_t)(n0 + lr) * KDIM + lk;
    const float* wp1 = wp0 + (size_t)64 * KDIM;

    float4 ra0, ra1, rb0, rb1;

#define STS_STAGE(buf) do {                                                     \
    As[buf][lk+0][lr]    = ra0.x; As[buf][lk+1][lr]    = ra0.y;                 \
    As[buf][lk+2][lr]    = ra0.z; As[buf][lk+3][lr]    = ra0.w;                 \
    As[buf][lk+0][lr+64] = ra1.x; As[buf][lk+1][lr+64] = ra1.y;                 \
    As[buf][lk+2][lr+64] = ra1.z; As[buf][lk+3][lr+64] = ra1.w;                 \
    Bs[buf][lk+0][lr]    = rb0.x; Bs[buf][lk+1][lr]    = rb0.y;                 \
    Bs[buf][lk+2][lr]    = rb0.z; Bs[buf][lk+3][lr]    = rb0.w;                 \
    Bs[buf][lk+0][lr+64] = rb1.x; Bs[buf][lk+1][lr+64] = rb1.y;                 \
    Bs[buf][lk+2][lr+64] = rb1.z; Bs[buf][lk+3][lr+64] = rb1.w;                 \
} while (0)

    int ty = tid >> 4;
    int tx = tid & 15;

    unsigned long long acc[8][4];
#pragma unroll
    for (int i = 0; i < 8; ++i)
#pragma unroll
        for (int j = 0; j < 4; ++j) acc[i][j] = 0ULL;

    // Prologue: slab 0
    ra0 = *(const float4*)(ap0);
    ra1 = *(const float4*)(ap1);
    rb0 = *(const float4*)(wp0);
    rb1 = *(const float4*)(wp1);
    STS_STAGE(0);
    __syncthreads();

    const int NSLAB = KDIM / 16;
#pragma unroll 1
    for (int ks = 0; ks < NSLAB; ++ks) {
        int cur = ks & 1;
        if (ks + 1 < NSLAB) {
            int koff = (ks + 1) * 16;
            ra0 = *(const float4*)(ap0 + koff);
            ra1 = *(const float4*)(ap1 + koff);
            rb0 = *(const float4*)(wp0 + koff);
            rb1 = *(const float4*)(wp1 + koff);
        }
#pragma unroll
        for (int k = 0; k < 16; ++k) {
            float4 a0 = *(const float4*)&As[cur][k][ty * 8];
            float4 a1 = *(const float4*)&As[cur][k][ty * 8 + 4];
            ulonglong2 b01 = *(const ulonglong2*)&Bs[cur][k][tx * 8];
            ulonglong2 b23 = *(const ulonglong2*)&Bs[cur][k][tx * 8 + 4];
            float av[8] = {a0.x, a0.y, a0.z, a0.w, a1.x, a1.y, a1.z, a1.w};
#pragma unroll
            for (int i = 0; i < 8; ++i) {
                unsigned long long aa;
                asm("mov.b64 %0, {%1, %1};" : "=l"(aa) : "r"(__float_as_uint(av[i])));
                asm("fma.rn.f32x2 %0, %1, %2, %0;" : "+l"(acc[i][0]) : "l"(aa), "l"(b01.x));
                asm("fma.rn.f32x2 %0, %1, %2, %0;" : "+l"(acc[i][1]) : "l"(aa), "l"(b01.y));
                asm("fma.rn.f32x2 %0, %1, %2, %0;" : "+l"(acc[i][2]) : "l"(aa), "l"(b23.x));
                asm("fma.rn.f32x2 %0, %1, %2, %0;" : "+l"(acc[i][3]) : "l"(aa), "l"(b23.y));
            }
        }
        if (ks + 1 < NSLAB) STS_STAGE((ks + 1) & 1);
        __syncthreads();
    }
#undef STS_STAGE

    // Epilogue
#pragma unroll
    for (int i = 0; i < 8; ++i) {
        int sl = s_slot[ty * 8 + i];
        if (sl < 0) continue;
        float* crow = Cbase + (size_t)sl * NDIM + n0 + tx * 8;
#pragma unroll
        for (int jp = 0; jp < 4; ++jp) {
            union { unsigned long long u; float2 f; } cv;
            cv.u = acc[i][jp];
            float2 v = cv.f;
            if (RELU2) {
                v.x = fmaxf(v.x, 0.f); v.x *= v.x;
                v.y = fmaxf(v.y, 0.f); v.y *= v.y;
            }
            *(float2*)(crow + jp * 2) = v;
        }
    }
}

// ---------------------------------------------------------------------------
__global__ void k_combine(float* __restrict__ out, int out_size) {
    int t = blockIdx.x;
    int i = threadIdx.x;
    float w0 = g_w[2 * t];
    float w1 = g_w[2 * t + 1];
    float4 a = ((const float4*)(g_y + (size_t)(2 * t) * DIMSZ))[i];
    float4 b = ((const float4*)(g_y + (size_t)(2 * t + 1) * DIMSZ))[i];
    float4 r;
    r.x = w0 * a.x + w1 * b.x;
    r.y = w0 * a.y + w1 * b.y;
    r.z = w0 * a.z + w1 * b.z;
    r.w = w0 * a.w + w1 * b.w;
    ((float4*)(out + (size_t)t * DIMSZ))[i] = r;
    if (t == 0 && i == 0) {
        for (int j = TOK * DIMSZ; j < out_size; ++j) out[j] = 0.f;  // aux_loss tail
    }
}

// ---------------------------------------------------------------------------
extern "C" void kernel_launch(void* const* d_in, const int* in_sizes, int n_in,
                              void* d_out, int out_size) {
    const float* x   = (const float*)d_in[0];   // [1, 2048, 1024]
    const float* Wr  = (const float*)d_in[1];   // [8, 1024]
    const float* Wfc = (const float*)d_in[2];   // [8, 2048, 1024]
    const float* Wp  = (const float*)d_in[3];   // [8, 1024, 2048]
    float* out = (float*)d_out;

    k_zero_counts<<<1, 32>>>();
    k_router<<<TOK / 8, 256>>>(x, Wr);
    // GEMM1: h2[slot, H] = relu(x[tok] @ Wfc[e]^T)^2
    k_gemm<DIMSZ, HID, true, 1, 1><<<dim3(HID / 128, TOK / 128, NE), 256>>>(x, Wfc);
    // GEMM2: y[slot, D] = h2[slot] @ Wp[e]^T
    k_gemm<HID, DIMSZ, false, 0, 2><<<dim3(DIMSZ / 128, TOK / 128, NE), 256>>>(nullptr, Wp);
    k_combine<<<TOK, 256>>>(out, out_size);
}

// round 3
// speedup vs baseline: 1.0692x; 1.0692x over previous
#include <cuda_runtime.h>
#include <cstdint>

#define TOK   2048
#define DIMSZ 1024
#define HID   2048
#define NE    8
#define NSLOT (2 * TOK)

// Scratch (allocation-free: __device__ globals)
__device__ float g_w[NSLOT];
__device__ int   g_cnt[NE];
__device__ int   g_list[NE * TOK];
__device__ float g_h2[(size_t)NSLOT * HID];
__device__ float g_y [(size_t)NSLOT * DIMSZ];

// ---------------------------------------------------------------------------
// Helpers
// ---------------------------------------------------------------------------
__device__ __forceinline__ uint32_t smem_u32(const void* p) {
    uint32_t a;
    asm("{ .reg .u64 t; cvta.to.shared.u64 t, %1; cvt.u32.u64 %0, t; }" : "=r"(a) : "l"(p));
    return a;
}
// pack two f32 -> bf16x2 (memory order: lo_elem in lower half)
__device__ __forceinline__ uint32_t bfpack(float lo_elem, float hi_elem) {
    uint32_t r;
    asm("cvt.rn.bf16x2.f32 %0, %1, %2;" : "=r"(r) : "f"(hi_elem), "f"(lo_elem));
    return r;
}
__device__ __forceinline__ void ldm4(uint32_t* r, uint32_t addr) {
    asm volatile("ldmatrix.sync.aligned.m8n8.x4.shared.b16 {%0,%1,%2,%3}, [%4];"
        : "=r"(r[0]), "=r"(r[1]), "=r"(r[2]), "=r"(r[3]) : "r"(addr));
}
__device__ __forceinline__ void ldm2(uint32_t* r, uint32_t addr) {
    asm volatile("ldmatrix.sync.aligned.m8n8.x2.shared.b16 {%0,%1}, [%2];"
        : "=r"(r[0]), "=r"(r[1]) : "r"(addr));
}
__device__ __forceinline__ void mma16816(float* c, const uint32_t* a, const uint32_t* b) {
    asm volatile(
        "mma.sync.aligned.m16n8k16.row.col.f32.bf16.bf16.f32 "
        "{%0,%1,%2,%3}, {%4,%5,%6,%7}, {%8,%9}, {%0,%1,%2,%3};"
        : "+f"(c[0]), "+f"(c[1]), "+f"(c[2]), "+f"(c[3])
        : "r"(a[0]), "r"(a[1]), "r"(a[2]), "r"(a[3]), "r"(b[0]), "r"(b[1]));
}

// ---------------------------------------------------------------------------
__global__ void k_zero_counts() {
    if (threadIdx.x < NE) g_cnt[threadIdx.x] = 0;
}

// Router: one warp per token. logits -> softmax -> top2 -> renormalize (+1e-8)
__global__ void k_router(const float* __restrict__ x, const float* __restrict__ Wr) {
    int warp = threadIdx.x >> 5;
    int lane = threadIdx.x & 31;
    int t = blockIdx.x * 8 + warp;

    float acc[NE];
#pragma unroll
    for (int e = 0; e < NE; ++e) acc[e] = 0.f;

    const float* xr = x + (size_t)t * DIMSZ;
    for (int i = lane; i < DIMSZ; i += 32) {
        float xv = xr[i];
#pragma unroll
        for (int e = 0; e < NE; ++e) acc[e] = fmaf(xv, Wr[e * DIMSZ + i], acc[e]);
    }
#pragma unroll
    for (int e = 0; e < NE; ++e) {
#pragma unroll
        for (int o = 16; o > 0; o >>= 1)
            acc[e] += __shfl_xor_sync(0xffffffffu, acc[e], o);
    }
    if (lane == 0) {
        float m = acc[0];
#pragma unroll
        for (int e = 1; e < NE; ++e) m = fmaxf(m, acc[e]);
        float p[NE]; float Z = 0.f;
#pragma unroll
        for (int e = 0; e < NE; ++e) { p[e] = expf(acc[e] - m); Z += p[e]; }
        float invZ = 1.f / Z;
#pragma unroll
        for (int e = 0; e < NE; ++e) p[e] *= invZ;

        int e0 = 0;
#pragma unroll
        for (int e = 1; e < NE; ++e) if (p[e] > p[e0]) e0 = e;
        int e1 = (e0 == 0) ? 1 : 0;
#pragma unroll
        for (int e = 0; e < NE; ++e) { if (e != e0 && p[e] > p[e1]) e1 = e; }

        float s = p[e0] + p[e1] + 1e-8f;
        g_w[2 * t]     = p[e0] / s;
        g_w[2 * t + 1] = p[e1] / s;
        int q0 = atomicAdd(&g_cnt[e0], 1); g_list[e0 * TOK + q0] = 2 * t;
        int q1 = atomicAdd(&g_cnt[e1], 1); g_list[e1 * TOK + q1] = 2 * t + 1;
    }
}

// ---------------------------------------------------------------------------
// Grouped GEMM via mma.sync.m16n8k16 bf16, 3-term precision split:
//   C = Ah*Bh + Ah*Bl + Al*Bh   (fp32 accumulate; dropped Al*Bl ~ 2^-18)
// 128x128 CTA tile, 256 threads (8 warps, 2x4), warp tile 64x32.
// Smem: per stage: Ah,Al,Bh,Bl each 128 rows x 32 bf16, row pitch 80B.
// PHASE 1: A = x (row = slot>>1), C = g_h2, relu^2 epilogue
// PHASE 2: A = g_h2 (row = slot),  C = g_y
#define RPITCH   80
#define MAT_SZ   (128 * RPITCH)     // 10240
#define AH_OFF   0
#define AL_OFF   (1 * MAT_SZ)
#define BH_OFF   (2 * MAT_SZ)
#define BL_OFF   (3 * MAT_SZ)
#define ST_STRIDE (4 * MAT_SZ)      // 40960
#define SLOT_OFF (2 * ST_STRIDE)    // 81920
#define AOFF_OFF (SLOT_OFF + 512)
#define GT_SMEM  (AOFF_OFF + 512 + 32)

template<int KDIM, int NDIM, bool RELU2, int SHIFT, int PHASE>
__global__ void __launch_bounds__(256, 1)
k_gemm_mma(const float* __restrict__ Ain, const float* __restrict__ Wall) {
    constexpr int NSLAB = KDIM / 32;
    const float* Abase = (PHASE == 1) ? Ain : (const float*)g_h2;
    float*       Cbase = (PHASE == 1) ? (float*)g_h2 : (float*)g_y;

    int e   = blockIdx.z;
    int cnt = g_cnt[e];
    int m0  = blockIdx.y * 128;
    if (m0 >= cnt) return;
    int n0  = blockIdx.x * 128;
    const float* W = Wall + (size_t)e * NDIM * KDIM;

    extern __shared__ char smem[];
    int* s_slot = (int*)(smem + SLOT_OFF);
    int* s_aoff = (int*)(smem + AOFF_OFF);
    int tid = threadIdx.x;

    if (tid < 128) {
        int idx = m0 + tid;
        int sl  = g_list[e * TOK + ((idx < cnt) ? idx : m0)];
        s_slot[tid] = (idx < cnt) ? sl : -1;
        s_aoff[tid] = (sl >> SHIFT) * KDIM;
    }
    __syncthreads();

    // Loader: thread t<128 owns A row t; t>=128 owns B row (t-128). 32 f32/slab.
    int lrow = tid & 127;
    const float* src = (tid < 128) ? (Abase + s_aoff[lrow])
                                   : (W + (size_t)(n0 + lrow) * KDIM);
    char* dstH = smem + ((tid < 128) ? AH_OFF : BH_OFF) + lrow * RPITCH;

    float4 v[8];

    auto lds_slab = [&](int k0) {
#pragma unroll
        for (int j = 0; j < 8; ++j) v[j] = *(const float4*)(src + k0 + j * 4);
    };
    auto sts_slab = [&](int stage) {
        char* p = dstH + stage * ST_STRIDE;
#pragma unroll
        for (int j = 0; j < 8; ++j) {
            float4 a = v[j];
            uint32_t h01 = bfpack(a.x, a.y);
            uint32_t h23 = bfpack(a.z, a.w);
            float rx = a.x - __uint_as_float(h01 << 16);
            float ry = a.y - __uint_as_float(h01 & 0xffff0000u);
            float rz = a.z - __uint_as_float(h23 << 16);
            float rw = a.w - __uint_as_float(h23 & 0xffff0000u);
            uint32_t l01 = bfpack(rx, ry);
            uint32_t l23 = bfpack(rz, rw);
            *(uint2*)(p + j * 8)          = make_uint2(h01, h23);
            *(uint2*)(p + MAT_SZ + j * 8) = make_uint2(l01, l23);
        }
    };

    lds_slab(0);
    sts_slab(0);
    __syncthreads();

    int wid  = tid >> 5, lane = tid & 31;
    int wy   = wid >> 2, wx = wid & 3;
    uint32_t sb = smem_u32(smem);
    // ldmatrix lane address bases (bytes)
    uint32_t aAddr = sb + AH_OFF + (uint32_t)(wy * 64 + (lane & 15)) * RPITCH + (lane >> 4) * 16;
    uint32_t bAddr = sb + BH_OFF + (uint32_t)(wx * 32 + (lane & 7))  * RPITCH + ((lane >> 3) & 1) * 16;

    float acc[4][4][4];
#pragma unroll
    for (int i = 0; i < 4; ++i)
#pragma unroll
        for (int j = 0; j < 4; ++j)
#pragma unroll
            for (int r = 0; r < 4; ++r) acc[i][j][r] = 0.f;

#pragma unroll 1
    for (int ks = 0; ks < NSLAB; ++ks) {
        int cur = ks & 1;
        if (ks + 1 < NSLAB) lds_slab((ks + 1) * 32);

        uint32_t aS = aAddr + cur * ST_STRIDE;
        uint32_t bS = bAddr + cur * ST_STRIDE;
#pragma unroll
        for (int kk = 0; kk < 2; ++kk) {
            uint32_t ah[4][4], al[4][4], bh[4][2], bl[4][2];
#pragma unroll
            for (int mt = 0; mt < 4; ++mt) {
                ldm4(ah[mt], aS + mt * (16 * RPITCH) + kk * 32);
                ldm4(al[mt], aS + mt * (16 * RPITCH) + kk * 32 + MAT_SZ);
            }
#pragma unroll
            for (int nt = 0; nt < 4; ++nt) {
                ldm2(bh[nt], bS + nt * (8 * RPITCH) + kk * 32);
                ldm2(bl[nt], bS + nt * (8 * RPITCH) + kk * 32 + MAT_SZ);
            }
#pragma unroll
            for (int mt = 0; mt < 4; ++mt)
#pragma unroll
                for (int nt = 0; nt < 4; ++nt) {
                    mma16816(acc[mt][nt], ah[mt], bh[nt]);
                    mma16816(acc[mt][nt], ah[mt], bl[nt]);
                    mma16816(acc[mt][nt], al[mt], bh[nt]);
                }
        }
        if (ks + 1 < NSLAB) sts_slab((ks + 1) & 1);
        __syncthreads();
    }

    // Epilogue: C frag c0,c1 = (row t/4, cols (t%4)*2 +0/1); c2,c3 = row t/4+8
#pragma unroll
    for (int mt = 0; mt < 4; ++mt) {
        int lm = wy * 64 + mt * 16 + (lane >> 2);
#pragma unroll
        for (int half = 0; half < 2; ++half) {
            int sl = s_slot[lm + half * 8];
            if (sl < 0) continue;
            float* crow = Cbase + (size_t)sl * NDIM + n0 + wx * 32 + (lane & 3) * 2;
#pragma unroll
            for (int nt = 0; nt < 4; ++nt) {
                float2 pv;
                pv.x = acc[mt][nt][half * 2 + 0];
                pv.y = acc[mt][nt][half * 2 + 1];
                if (RELU2) {
                    pv.x = fmaxf(pv.x, 0.f); pv.x *= pv.x;
                    pv.y = fmaxf(pv.y, 0.f); pv.y *= pv.y;
                }
                *(float2*)(crow + nt * 8) = pv;
            }
        }
    }
}

// ---------------------------------------------------------------------------
__global__ void k_combine(float* __restrict__ out, int out_size) {
    int t = blockIdx.x;
    int i = threadIdx.x;
    float w0 = g_w[2 * t];
    float w1 = g_w[2 * t + 1];
    float4 a = ((const float4*)(g_y + (size_t)(2 * t) * DIMSZ))[i];
    float4 b = ((const float4*)(g_y + (size_t)(2 * t + 1) * DIMSZ))[i];
    float4 r;
    r.x = w0 * a.x + w1 * b.x;
    r.y = w0 * a.y + w1 * b.y;
    r.z = w0 * a.z + w1 * b.z;
    r.w = w0 * a.w + w1 * b.w;
    ((float4*)(out + (size_t)t * DIMSZ))[i] = r;
    if (t == 0 && i == 0) {
        for (int j = TOK * DIMSZ; j < out_size; ++j) out[j] = 0.f;  // aux_loss tail
    }
}

// ---------------------------------------------------------------------------
extern "C" void kernel_launch(void* const* d_in, const int* in_sizes, int n_in,
                              void* d_out, int out_size) {
    const float* x   = (const float*)d_in[0];   // [1, 2048, 1024]
    const float* Wr  = (const float*)d_in[1];   // [8, 1024]
    const float* Wfc = (const float*)d_in[2];   // [8, 2048, 1024]
    const float* Wp  = (const float*)d_in[3];   // [8, 1024, 2048]
    float* out = (float*)d_out;

    cudaFuncSetAttribute(k_gemm_mma<DIMSZ, HID, true, 1, 1>,
                         cudaFuncAttributeMaxDynamicSharedMemorySize, GT_SMEM);
    cudaFuncSetAttribute(k_gemm_mma<HID, DIMSZ, false, 0, 2>,
                         cudaFuncAttributeMaxDynamicSharedMemorySize, GT_SMEM);

    k_zero_counts<<<1, 32>>>();
    k_router<<<TOK / 8, 256>>>(x, Wr);
    // GEMM1: h2[slot, H] = relu(x[tok] @ Wfc[e]^T)^2
    k_gemm_mma<DIMSZ, HID, true, 1, 1>
        <<<dim3(HID / 128, TOK / 128, NE), 256, GT_SMEM>>>(x, Wfc);
    // GEMM2: y[slot, D] = h2[slot] @ Wp[e]^T
    k_gemm_mma<HID, DIMSZ, false, 0, 2>
        <<<dim3(DIMSZ / 128, TOK / 128, NE), 256, GT_SMEM>>>(nullptr, Wp);
    k_combine<<<TOK, 256>>>(out, out_size);
}

// round 4
// speedup vs baseline: 2.3879x; 2.2334x over previous
#include <cuda_runtime.h>
#include <cuda_bf16.h>
#include <cstdint>

#define TOK   2048
#define DIMSZ 1024
#define HID   2048
#define NE    8
#define NSLOT (2 * TOK)

// Scratch (allocation-free: __device__ globals)
__device__ float g_w[NSLOT];
__device__ int   g_cnt[NE];
__device__ int   g_list[NE * TOK];
__device__ __align__(128) __nv_bfloat16 g_xh[TOK * DIMSZ];
__device__ __align__(128) __nv_bfloat16 g_xl[TOK * DIMSZ];
__device__ __align__(128) __nv_bfloat16 g_wfch[NE * HID * DIMSZ];
__device__ __align__(128) __nv_bfloat16 g_wfcl[NE * HID * DIMSZ];
__device__ __align__(128) __nv_bfloat16 g_wph[NE * DIMSZ * HID];
__device__ __align__(128) __nv_bfloat16 g_wpl[NE * DIMSZ * HID];
__device__ __align__(128) __nv_bfloat16 g_h2h[NSLOT * HID];
__device__ __align__(128) __nv_bfloat16 g_h2l[NSLOT * HID];
__device__ float g_y[(size_t)NSLOT * DIMSZ];

// ---------------------------------------------------------------------------
// Helpers
// ---------------------------------------------------------------------------
__device__ __forceinline__ uint32_t smem_u32(const void* p) {
    uint32_t a;
    asm("{ .reg .u64 t; cvta.to.shared.u64 t, %1; cvt.u32.u64 %0, t; }" : "=r"(a) : "l"(p));
    return a;
}
// pack two f32 -> bf16x2 (elem0 in low half)
__device__ __forceinline__ uint32_t bfpack(float e0, float e1) {
    uint32_t r;
    asm("cvt.rn.bf16x2.f32 %0, %1, %2;" : "=r"(r) : "f"(e1), "f"(e0));
    return r;
}
__device__ __forceinline__ void ldm4(uint32_t* r, uint32_t addr) {
    asm volatile("ldmatrix.sync.aligned.m8n8.x4.shared.b16 {%0,%1,%2,%3}, [%4];"
        : "=r"(r[0]), "=r"(r[1]), "=r"(r[2]), "=r"(r[3]) : "r"(addr));
}
__device__ __forceinline__ void ldm2(uint32_t* r, uint32_t addr) {
    asm volatile("ldmatrix.sync.aligned.m8n8.x2.shared.b16 {%0,%1}, [%2];"
        : "=r"(r[0]), "=r"(r[1]) : "r"(addr));
}
__device__ __forceinline__ void mma16816(float* c, const uint32_t* a, const uint32_t* b) {
    asm volatile(
        "mma.sync.aligned.m16n8k16.row.col.f32.bf16.bf16.f32 "
        "{%0,%1,%2,%3}, {%4,%5,%6,%7}, {%8,%9}, {%0,%1,%2,%3};"
        : "+f"(c[0]), "+f"(c[1]), "+f"(c[2]), "+f"(c[3])
        : "r"(a[0]), "r"(a[1]), "r"(a[2]), "r"(a[3]), "r"(b[0]), "r"(b[1]));
}
__device__ __forceinline__ void cp16(uint32_t dst, const void* src) {
    asm volatile("cp.async.cg.shared.global [%0], [%1], 16;" :: "r"(dst), "l"(src) : "memory");
}
__device__ __forceinline__ void cp_commit() {
    asm volatile("cp.async.commit_group;" ::: "memory");
}
template<int N> __device__ __forceinline__ void cp_wait() {
    asm volatile("cp.async.wait_group %0;" :: "n"(N) : "memory");
}
// (row, 16B-chunk c in 0..3) -> swizzled byte offset within one 128x64B mat
__device__ __forceinline__ uint32_t swzoff(uint32_t row, uint32_t c) {
    uint32_t q = (((row & 1u) << 2) | c) ^ ((row >> 1) & 7u);
    return ((row >> 1) << 7) + (q << 4);
}

// ---------------------------------------------------------------------------
__global__ void k_zero_counts() {
    if (threadIdx.x < NE) g_cnt[threadIdx.x] = 0;
}

// Pre-split fp32 -> bf16 hi/lo pairs. SEL: 0=x, 1=Wfc, 2=Wp
template<int SEL>
__global__ void k_split(const float4* __restrict__ s, int n4) {
    int i = blockIdx.x * 256 + threadIdx.x;
    if (i >= n4) return;
    uint2* dh = (SEL == 0) ? (uint2*)g_xh : (SEL == 1) ? (uint2*)g_wfch : (uint2*)g_wph;
    uint2* dl = (SEL == 0) ? (uint2*)g_xl : (SEL == 1) ? (uint2*)g_wfcl : (uint2*)g_wpl;
    float4 v = s[i];
    uint32_t h01 = bfpack(v.x, v.y);
    uint32_t h23 = bfpack(v.z, v.w);
    float rx = v.x - __uint_as_float(h01 << 16);
    float ry = v.y - __uint_as_float(h01 & 0xffff0000u);
    float rz = v.z - __uint_as_float(h23 << 16);
    float rw = v.w - __uint_as_float(h23 & 0xffff0000u);
    dh[i] = make_uint2(h01, h23);
    dl[i] = make_uint2(bfpack(rx, ry), bfpack(rz, rw));
}

// Router: one warp per token. logits -> softmax -> top2 -> renormalize (+1e-8)
__global__ void k_router(const float* __restrict__ x, const float* __restrict__ Wr) {
    int warp = threadIdx.x >> 5;
    int lane = threadIdx.x & 31;
    int t = blockIdx.x * 8 + warp;

    float acc[NE];
#pragma unroll
    for (int e = 0; e < NE; ++e) acc[e] = 0.f;

    const float* xr = x + (size_t)t * DIMSZ;
    for (int i = lane; i < DIMSZ; i += 32) {
        float xv = xr[i];
#pragma unroll
        for (int e = 0; e < NE; ++e) acc[e] = fmaf(xv, Wr[e * DIMSZ + i], acc[e]);
    }
#pragma unroll
    for (int e = 0; e < NE; ++e) {
#pragma unroll
        for (int o = 16; o > 0; o >>= 1)
            acc[e] += __shfl_xor_sync(0xffffffffu, acc[e], o);
    }
    if (lane == 0) {
        float m = acc[0];
#pragma unroll
        for (int e = 1; e < NE; ++e) m = fmaxf(m, acc[e]);
        float p[NE]; float Z = 0.f;
#pragma unroll
        for (int e = 0; e < NE; ++e) { p[e] = expf(acc[e] - m); Z += p[e]; }
        float invZ = 1.f / Z;
#pragma unroll
        for (int e = 0; e < NE; ++e) p[e] *= invZ;

        int e0 = 0;
#pragma unroll
        for (int e = 1; e < NE; ++e) if (p[e] > p[e0]) e0 = e;
        int e1 = (e0 == 0) ? 1 : 0;
#pragma unroll
        for (int e = 0; e < NE; ++e) { if (e != e0 && p[e] > p[e1]) e1 = e; }

        float s = p[e0] + p[e1] + 1e-8f;
        g_w[2 * t]     = p[e0] / s;
        g_w[2 * t + 1] = p[e1] / s;
        int q0 = atomicAdd(&g_cnt[e0], 1); g_list[e0 * TOK + q0] = 2 * t;
        int q1 = atomicAdd(&g_cnt[e1], 1); g_list[e1 * TOK + q1] = 2 * t + 1;
    }
}

// ---------------------------------------------------------------------------
// Grouped GEMM: mma.sync m16n8k16 bf16, 3-term split (Ah·Bh + Ah·Bl + Al·Bh).
// All operands pre-split to bf16 hi/lo; loader is pure cp.async.cg.
// CTA = 128 threads (4 warps 2x2), tile 128x128, warp tile 64x64.
// Smem per stage: mats Ah, Al, Bh, Bl, each 128 rows x 64B, XOR-swizzled.
#define MAT      8192
#define STG      (4 * MAT)            // 32768
#define SLOT_OFF (2 * STG)            // 65536
#define AOFF_OFF (SLOT_OFF + 512)
#define GSMEM    (AOFF_OFF + 512)

template<int KDIM, int NDIM, bool RELU2, int SHIFT, int PHASE>
__global__ void __launch_bounds__(128, 2)
k_gemm_mma() {
    constexpr int NSLAB = KDIM / 32;
    const __nv_bfloat16* Ah = (PHASE == 1) ? g_xh : g_h2h;
    const __nv_bfloat16* Al = (PHASE == 1) ? g_xl : g_h2l;
    const __nv_bfloat16* BhA = (PHASE == 1) ? g_wfch : g_wph;
    const __nv_bfloat16* BlA = (PHASE == 1) ? g_wfcl : g_wpl;

    int e   = blockIdx.z;
    int cnt = g_cnt[e];
    int m0  = blockIdx.y * 128;
    if (m0 >= cnt) return;
    int n0  = blockIdx.x * 128;
    const __nv_bfloat16* Bh = BhA + (size_t)e * NDIM * KDIM;
    const __nv_bfloat16* Bl = BlA + (size_t)e * NDIM * KDIM;

    extern __shared__ char smem[];
    uint32_t sb = smem_u32(smem);
    int* s_slot = (int*)(smem + SLOT_OFF);
    int* s_aoff = (int*)(smem + AOFF_OFF);
    int tid = threadIdx.x, w = tid >> 5, lane = tid & 31;

    {
        int idx = m0 + tid;
        int sl  = g_list[e * TOK + ((idx < cnt) ? idx : m0)];
        s_slot[tid] = (idx < cnt) ? sl : -1;
        s_aoff[tid] = (sl >> SHIFT) * KDIM;
    }
    __syncthreads();

    int lrow = lane & 7, lchunk = lane >> 3;
    int raoff[4];
#pragma unroll
    for (int j = 0; j < 4; ++j) raoff[j] = s_aoff[(4 * j + w) * 8 + lrow];

    // issue one K-slab (32 bf16 per row) into a stage: 16 cp.async per thread
    auto issue = [&](int ks, int stage) {
        int k0 = ks * 32;
        uint32_t stg = sb + stage * STG;
#pragma unroll
        for (int i = 0; i < 16; ++i) {
            int mat = i & 3, j = i >> 2;
            uint32_t row = (uint32_t)(4 * j + w) * 8 + lrow;
            uint32_t dst = stg + mat * MAT + swzoff(row, lchunk);
            const __nv_bfloat16* src;
            if (mat == 0)      src = Ah + raoff[j] + k0;
            else if (mat == 1) src = Al + raoff[j] + k0;
            else if (mat == 2) src = Bh + (size_t)(n0 + row) * KDIM + k0;
            else               src = Bl + (size_t)(n0 + row) * KDIM + k0;
            cp16(dst, src + lchunk * 8);
        }
        cp_commit();
    };

    issue(0, 0);
    issue(1, 1);
    cp_wait<1>();
    __syncthreads();

    int wy = w >> 1, wx = w & 1;
    // ldmatrix per-lane bases (kk=0); kk=1 via ^0x20, mats via +MAT
    uint32_t aQ = (((lane & 1u) << 2) | (uint32_t)(lane >> 4)) ^ (((uint32_t)(lane & 15) >> 1) & 7u);
    uint32_t aB0 = sb + (uint32_t)((wy * 64 + (lane & 15)) >> 1) * 128 + aQ * 16;
    uint32_t bQ = (((lane & 1u) << 2) | ((uint32_t)(lane >> 3) & 1u)) ^ ((uint32_t)(lane & 7) >> 1);
    uint32_t bB0 = sb + 2 * MAT + (uint32_t)((wx * 64 + (lane & 7)) >> 1) * 128 + bQ * 16;

    float acc[4][8][4];
#pragma unroll
    for (int i = 0; i < 4; ++i)
#pragma unroll
        for (int j = 0; j < 8; ++j)
#pragma unroll
            for (int r = 0; r < 4; ++r) acc[i][j][r] = 0.f;

#pragma unroll 1
    for (int ks = 0; ks < NSLAB; ++ks) {
        int cur = ks & 1;
        uint32_t aS = aB0 + cur * STG;
        uint32_t bS = bB0 + cur * STG;
#pragma unroll
        for (int kk = 0; kk < 2; ++kk) {
            uint32_t ah[4][4], al[4][4];
#pragma unroll
            for (int mt = 0; mt < 4; ++mt) {
                uint32_t ad = (aS + mt * 1024) ^ (kk * 0x20);
                ldm4(ah[mt], ad);
                ldm4(al[mt], ad + MAT);
            }
#pragma unroll
            for (int ntg = 0; ntg < 2; ++ntg) {
                uint32_t bh[4][2], bl[4][2];
#pragma unroll
                for (int nt = 0; nt < 4; ++nt) {
                    uint32_t bd = (bS + (ntg * 32 + nt * 8) * 64) ^ (kk * 0x20) ^ ((nt & 1) << 6);
                    ldm2(bh[nt], bd);
                    ldm2(bl[nt], bd + MAT);
                }
#pragma unroll
                for (int mt = 0; mt < 4; ++mt)
#pragma unroll
                    for (int nt = 0; nt < 4; ++nt) {
                        float* c = acc[mt][ntg * 4 + nt];
                        mma16816(c, ah[mt], bh[nt]);
                        mma16816(c, ah[mt], bl[nt]);
                        mma16816(c, al[mt], bh[nt]);
                    }
            }
        }
        __syncthreads();
        if (ks + 2 < NSLAB) { issue(ks + 2, cur); cp_wait<1>(); }
        else                { cp_wait<0>(); }
        __syncthreads();
    }

    // Epilogue
    int rbase = wy * 64 + (lane >> 2);
    int cbase = n0 + wx * 64 + (lane & 3) * 2;
#pragma unroll
    for (int mt = 0; mt < 4; ++mt) {
#pragma unroll
        for (int half = 0; half < 2; ++half) {
            int sl = s_slot[rbase + mt * 16 + half * 8];
            if (sl < 0) continue;
            if (RELU2) {
                uint32_t* oh = (uint32_t*)(g_h2h + (size_t)sl * NDIM + cbase);
                uint32_t* ol = (uint32_t*)(g_h2l + (size_t)sl * NDIM + cbase);
#pragma unroll
                for (int nt = 0; nt < 8; ++nt) {
                    float v0 = acc[mt][nt][half * 2 + 0];
                    float v1 = acc[mt][nt][half * 2 + 1];
                    v0 = fmaxf(v0, 0.f); v0 *= v0;
                    v1 = fmaxf(v1, 0.f); v1 *= v1;
                    uint32_t hp = bfpack(v0, v1);
                    float r0 = v0 - __uint_as_float(hp << 16);
                    float r1 = v1 - __uint_as_float(hp & 0xffff0000u);
                    oh[nt * 4] = hp;
                    ol[nt * 4] = bfpack(r0, r1);
                }
            } else {
                float* oy = g_y + (size_t)sl * NDIM + cbase;
#pragma unroll
                for (int nt = 0; nt < 8; ++nt) {
                    *(float2*)(oy + nt * 8) =
                        make_float2(acc[mt][nt][half * 2 + 0], acc[mt][nt][half * 2 + 1]);
                }
            }
        }
    }
}

// ---------------------------------------------------------------------------
__global__ void k_combine(float* __restrict__ out, int out_size) {
    int t = blockIdx.x;
    int i = threadIdx.x;
    float w0 = g_w[2 * t];
    float w1 = g_w[2 * t + 1];
    float4 a = ((const float4*)(g_y + (size_t)(2 * t) * DIMSZ))[i];
    float4 b = ((const float4*)(g_y + (size_t)(2 * t + 1) * DIMSZ))[i];
    float4 r;
    r.x = w0 * a.x + w1 * b.x;
    r.y = w0 * a.y + w1 * b.y;
    r.z = w0 * a.z + w1 * b.z;
    r.w = w0 * a.w + w1 * b.w;
    ((float4*)(out + (size_t)t * DIMSZ))[i] = r;
    if (t == 0 && i == 0) {
        for (int j = TOK * DIMSZ; j < out_size; ++j) out[j] = 0.f;  // aux_loss tail
    }
}

// ---------------------------------------------------------------------------
extern "C" void kernel_launch(void* const* d_in, const int* in_sizes, int n_in,
                              void* d_out, int out_size) {
    const float* x   = (const float*)d_in[0];   // [1, 2048, 1024]
    const float* Wr  = (const float*)d_in[1];   // [8, 1024]
    const float* Wfc = (const float*)d_in[2];   // [8, 2048, 1024]
    const float* Wp  = (const float*)d_in[3];   // [8, 1024, 2048]
    float* out = (float*)d_out;

    cudaFuncSetAttribute(k_gemm_mma<DIMSZ, HID, true, 1, 1>,
                         cudaFuncAttributeMaxDynamicSharedMemorySize, GSMEM);
    cudaFuncSetAttribute(k_gemm_mma<HID, DIMSZ, false, 0, 2>,
                         cudaFuncAttributeMaxDynamicSharedMemorySize, GSMEM);

    k_zero_counts<<<1, 32>>>();
    k_router<<<TOK / 8, 256>>>(x, Wr);
    k_split<0><<<(TOK * DIMSZ / 4 + 255) / 256, 256>>>((const float4*)x, TOK * DIMSZ / 4);
    k_split<1><<<(NE * HID * DIMSZ / 4 + 255) / 256, 256>>>((const float4*)Wfc, NE * HID * DIMSZ / 4);
    k_split<2><<<(NE * DIMSZ * HID / 4 + 255) / 256, 256>>>((const float4*)Wp, NE * DIMSZ * HID / 4);
    // GEMM1: h2[slot, H] = relu(x[tok] @ Wfc[e]^T)^2  (bf16 hi/lo output)
    k_gemm_mma<DIMSZ, HID, true, 1, 1>
        <<<dim3(HID / 128, TOK / 128, NE), 128, GSMEM>>>();
    // GEMM2: y[slot, D] = h2[slot] @ Wp[e]^T
    k_gemm_mma<HID, DIMSZ, false, 0, 2>
        <<<dim3(DIMSZ / 128, TOK / 128, NE), 128, GSMEM>>>();
    k_combine<<<TOK, 256>>>(out, out_size);
}

// round 5
// speedup vs baseline: 2.5280x; 1.0587x over previous
#include <cuda_runtime.h>
#include <cuda_bf16.h>
#include <cstdint>

#define TOK   2048
#define DIMSZ 1024
#define HID   2048
#define NE    8
#define NSLOT (2 * TOK)

// Scratch (allocation-free: __device__ globals)
__device__ float g_w[NSLOT];
__device__ int   g_cnt[NE];
__device__ int   g_list[NE * TOK];
__device__ __align__(128) __nv_bfloat16 g_xh[TOK * DIMSZ];
__device__ __align__(128) __nv_bfloat16 g_xl[TOK * DIMSZ];
__device__ __align__(128) __nv_bfloat16 g_wfch[NE * HID * DIMSZ];
__device__ __align__(128) __nv_bfloat16 g_wfcl[NE * HID * DIMSZ];
__device__ __align__(128) __nv_bfloat16 g_wph[NE * DIMSZ * HID];
__device__ __align__(128) __nv_bfloat16 g_wpl[NE * DIMSZ * HID];
__device__ __align__(128) __nv_bfloat16 g_h2h[NSLOT * HID];
__device__ __align__(128) __nv_bfloat16 g_h2l[NSLOT * HID];
__device__ float g_y[(size_t)NSLOT * DIMSZ];

// ---------------------------------------------------------------------------
// Helpers
// ---------------------------------------------------------------------------
__device__ __forceinline__ uint32_t smem_u32(const void* p) {
    uint32_t a;
    asm("{ .reg .u64 t; cvta.to.shared.u64 t, %1; cvt.u32.u64 %0, t; }" : "=r"(a) : "l"(p));
    return a;
}
// pack two f32 -> bf16x2 (elem0 in low half)
__device__ __forceinline__ uint32_t bfpack(float e0, float e1) {
    uint32_t r;
    asm("cvt.rn.bf16x2.f32 %0, %1, %2;" : "=r"(r) : "f"(e1), "f"(e0));
    return r;
}
__device__ __forceinline__ void ldm4(uint32_t* r, uint32_t addr) {
    asm volatile("ldmatrix.sync.aligned.m8n8.x4.shared.b16 {%0,%1,%2,%3}, [%4];"
        : "=r"(r[0]), "=r"(r[1]), "=r"(r[2]), "=r"(r[3]) : "r"(addr));
}
__device__ __forceinline__ void mma16816(float* c, const uint32_t* a, const uint32_t* b) {
    asm volatile(
        "mma.sync.aligned.m16n8k16.row.col.f32.bf16.bf16.f32 "
        "{%0,%1,%2,%3}, {%4,%5,%6,%7}, {%8,%9}, {%0,%1,%2,%3};"
        : "+f"(c[0]), "+f"(c[1]), "+f"(c[2]), "+f"(c[3])
        : "r"(a[0]), "r"(a[1]), "r"(a[2]), "r"(a[3]), "r"(b[0]), "r"(b[1]));
}
__device__ __forceinline__ void cp16(uint32_t dst, const void* src) {
    asm volatile("cp.async.cg.shared.global [%0], [%1], 16;" :: "r"(dst), "l"(src) : "memory");
}
__device__ __forceinline__ void cp_commit() {
    asm volatile("cp.async.commit_group;" ::: "memory");
}
template<int N> __device__ __forceinline__ void cp_wait() {
    asm volatile("cp.async.wait_group %0;" :: "n"(N) : "memory");
}
// (row, 16B-chunk c in 0..3) -> swizzled byte offset within one 128x64B mat
__device__ __forceinline__ uint32_t swzoff(uint32_t row, uint32_t c) {
    uint32_t q = (((row & 1u) << 2) | c) ^ ((row >> 1) & 7u);
    return ((row >> 1) << 7) + (q << 4);
}

// ---------------------------------------------------------------------------
__global__ void k_zero_counts() {
    if (threadIdx.x < NE) g_cnt[threadIdx.x] = 0;
}

// Pre-split fp32 -> bf16 hi/lo pairs. SEL: 0=x, 1=Wfc, 2=Wp
template<int SEL>
__global__ void k_split(const float4* __restrict__ s, int n4) {
    int i = blockIdx.x * 256 + threadIdx.x;
    if (i >= n4) return;
    uint2* dh = (SEL == 0) ? (uint2*)g_xh : (SEL == 1) ? (uint2*)g_wfch : (uint2*)g_wph;
    uint2* dl = (SEL == 0) ? (uint2*)g_xl : (SEL == 1) ? (uint2*)g_wfcl : (uint2*)g_wpl;
    float4 v = s[i];
    uint32_t h01 = bfpack(v.x, v.y);
    uint32_t h23 = bfpack(v.z, v.w);
    float rx = v.x - __uint_as_float(h01 << 16);
    float ry = v.y - __uint_as_float(h01 & 0xffff0000u);
    float rz = v.z - __uint_as_float(h23 << 16);
    float rw = v.w - __uint_as_float(h23 & 0xffff0000u);
    dh[i] = make_uint2(h01, h23);
    dl[i] = make_uint2(bfpack(rx, ry), bfpack(rz, rw));
}

// Router: one warp per token. logits -> softmax -> top2 -> renormalize (+1e-8)
__global__ void k_router(const float* __restrict__ x, const float* __restrict__ Wr) {
    int warp = threadIdx.x >> 5;
    int lane = threadIdx.x & 31;
    int t = blockIdx.x * 8 + warp;

    float acc[NE];
#pragma unroll
    for (int e = 0; e < NE; ++e) acc[e] = 0.f;

    const float* xr = x + (size_t)t * DIMSZ;
    for (int i = lane; i < DIMSZ; i += 32) {
        float xv = xr[i];
#pragma unroll
        for (int e = 0; e < NE; ++e) acc[e] = fmaf(xv, Wr[e * DIMSZ + i], acc[e]);
    }
#pragma unroll
    for (int e = 0; e < NE; ++e) {
#pragma unroll
        for (int o = 16; o > 0; o >>= 1)
            acc[e] += __shfl_xor_sync(0xffffffffu, acc[e], o);
    }
    if (lane == 0) {
        float m = acc[0];
#pragma unroll
        for (int e = 1; e < NE; ++e) m = fmaxf(m, acc[e]);
        float p[NE]; float Z = 0.f;
#pragma unroll
        for (int e = 0; e < NE; ++e) { p[e] = expf(acc[e] - m); Z += p[e]; }
        float invZ = 1.f / Z;
#pragma unroll
        for (int e = 0; e < NE; ++e) p[e] *= invZ;

        int e0 = 0;
#pragma unroll
        for (int e = 1; e < NE; ++e) if (p[e] > p[e0]) e0 = e;
        int e1 = (e0 == 0) ? 1 : 0;
#pragma unroll
        for (int e = 0; e < NE; ++e) { if (e != e0 && p[e] > p[e1]) e1 = e; }

        float s = p[e0] + p[e1] + 1e-8f;
        g_w[2 * t]     = p[e0] / s;
        g_w[2 * t + 1] = p[e1] / s;
        int q0 = atomicAdd(&g_cnt[e0], 1); g_list[e0 * TOK + q0] = 2 * t;
        int q1 = atomicAdd(&g_cnt[e1], 1); g_list[e1 * TOK + q1] = 2 * t + 1;
    }
}

// ---------------------------------------------------------------------------
// Grouped GEMM: mma.sync m16n8k16 bf16, 3-term split (Ah·Bh + Ah·Bl + Al·Bh).
// All operands pre-split to bf16 hi/lo; loader is pure cp.async.cg.
// CTA = 128 threads (4 warps 2x2), tile 128x128, warp tile 64x64.
// 3-stage circular cp.async pipeline, ONE __syncthreads per K-slab.
// Smem per stage: mats Ah, Al, Bh, Bl, each 128 rows x 64B, XOR-swizzled.
#define MAT      8192
#define STG      (4 * MAT)            // 32768
#define SLOT_OFF (3 * STG)            // 98304
#define AOFF_OFF (SLOT_OFF + 512)
#define GSMEM    (AOFF_OFF + 512)

template<int KDIM, int NDIM, bool RELU2, int SHIFT, int PHASE>
__global__ void __launch_bounds__(128, 2)
k_gemm_mma() {
    constexpr int NSLAB = KDIM / 32;
    const __nv_bfloat16* Ah = (PHASE == 1) ? g_xh : g_h2h;
    const __nv_bfloat16* Al = (PHASE == 1) ? g_xl : g_h2l;
    const __nv_bfloat16* BhA = (PHASE == 1) ? g_wfch : g_wph;
    const __nv_bfloat16* BlA = (PHASE == 1) ? g_wfcl : g_wpl;

    int e   = blockIdx.z;
    int cnt = g_cnt[e];
    int m0  = blockIdx.y * 128;
    if (m0 >= cnt) return;
    int n0  = blockIdx.x * 128;
    const __nv_bfloat16* Bh = BhA + (size_t)e * NDIM * KDIM;
    const __nv_bfloat16* Bl = BlA + (size_t)e * NDIM * KDIM;

    extern __shared__ char smem[];
    uint32_t sb = smem_u32(smem);
    int* s_slot = (int*)(smem + SLOT_OFF);
    int* s_aoff = (int*)(smem + AOFF_OFF);
    int tid = threadIdx.x, w = tid >> 5, lane = tid & 31;

    {
        int idx = m0 + tid;
        int sl  = g_list[e * TOK + ((idx < cnt) ? idx : m0)];
        s_slot[tid] = (idx < cnt) ? sl : -1;
        s_aoff[tid] = (sl >> SHIFT) * KDIM;
    }
    __syncthreads();

    int lrow = lane & 7, lchunk = lane >> 3;
    int raoff[4];
    size_t boff[4];
#pragma unroll
    for (int j = 0; j < 4; ++j) {
        int row = (4 * j + w) * 8 + lrow;
        raoff[j] = s_aoff[row] + lchunk * 8;
        boff[j]  = (size_t)(n0 + row) * KDIM + lchunk * 8;
    }

    // issue one K-slab (32 bf16 per row) into a stage: 16 cp.async + 1 commit
    auto issue = [&](int ks, int stage) {
        int k0 = ks * 32;
        uint32_t stg = sb + (uint32_t)stage * STG;
#pragma unroll
        for (int j = 0; j < 4; ++j) {
            uint32_t row = (uint32_t)(4 * j + w) * 8 + lrow;
            uint32_t so = stg + swzoff(row, lchunk);
            cp16(so,           Ah + raoff[j] + k0);
            cp16(so + MAT,     Al + raoff[j] + k0);
            cp16(so + 2 * MAT, Bh + boff[j] + k0);
            cp16(so + 3 * MAT, Bl + boff[j] + k0);
        }
        cp_commit();
    };

    int wy = w >> 1, wx = w & 1;
    // ldmatrix per-lane bases (kk=0); kk=1 via ^0x20
    uint32_t aQ = (((lane & 1u) << 2) | (uint32_t)(lane >> 4)) ^ (((uint32_t)(lane & 15) >> 1) & 7u);
    uint32_t aB0 = sb + (uint32_t)((wy * 64 + (lane & 15)) >> 1) * 128 + aQ * 16;
    // B ldm4: pair p covers n-tiles 2p, 2p+1 (16 rows)
    uint32_t brow = (uint32_t)(wx * 64 + ((lane >> 4) & 1) * 8 + (lane & 7));
    uint32_t bc   = (uint32_t)((lane >> 3) & 1);
    uint32_t bQ   = (((brow & 1u) << 2) | bc) ^ ((brow >> 1) & 7u);
    uint32_t bB0  = sb + 2 * MAT + (brow >> 1) * 128 + bQ * 16;

    float acc[4][8][4];
#pragma unroll
    for (int i = 0; i < 4; ++i)
#pragma unroll
        for (int j = 0; j < 8; ++j)
#pragma unroll
            for (int r = 0; r < 4; ++r) acc[i][j][r] = 0.f;

    issue(0, 0);
    issue(1, 1);
    cp_wait<1>();
    __syncthreads();

#pragma unroll 1
    for (int ks = 0; ks < NSLAB; ++ks) {
        int cur = ks % 3;
        // refill the stage freed at the previous barrier (2 slabs in flight)
        if (ks + 2 < NSLAB) issue(ks + 2, (ks + 2) % 3);
        else                cp_commit();   // empty group keeps wait-count logic uniform

        uint32_t aS = aB0 + (uint32_t)cur * STG;
        uint32_t bS = bB0 + (uint32_t)cur * STG;
#pragma unroll
        for (int kk = 0; kk < 2; ++kk) {
            uint32_t ah[4][4], al[4][4], bh[4][4], bl[4][4];
#pragma unroll
            for (int mt = 0; mt < 4; ++mt) {
                uint32_t ad = (aS + mt * 1024) ^ (kk * 0x20);
                ldm4(ah[mt], ad);
                ldm4(al[mt], ad + MAT);
            }
#pragma unroll
            for (int p = 0; p < 4; ++p) {
                uint32_t bd = (bS + p * 1024) ^ (kk * 0x20);
                ldm4(bh[p], bd);
                ldm4(bl[p], bd + MAT);
            }
#pragma unroll
            for (int mt = 0; mt < 4; ++mt)
#pragma unroll
                for (int nt = 0; nt < 8; ++nt) {
                    float* c = acc[mt][nt];
                    const uint32_t* pbh = &bh[nt >> 1][(nt & 1) * 2];
                    const uint32_t* pbl = &bl[nt >> 1][(nt & 1) * 2];
                    mma16816(c, ah[mt], pbh);
                    mma16816(c, ah[mt], pbl);
                    mma16816(c, al[mt], pbh);
                }
        }
        cp_wait<1>();      // slab ks+1 landed
        __syncthreads();   // everyone done reading stage cur -> refillable next iter
    }

    // Epilogue
    int rbase = wy * 64 + (lane >> 2);
    int cbase = n0 + wx * 64 + (lane & 3) * 2;
#pragma unroll
    for (int mt = 0; mt < 4; ++mt) {
#pragma unroll
        for (int half = 0; half < 2; ++half) {
            int sl = s_slot[rbase + mt * 16 + half * 8];
            if (sl < 0) continue;
            if (RELU2) {
                uint32_t* oh = (uint32_t*)(g_h2h + (size_t)sl * NDIM + cbase);
                uint32_t* ol = (uint32_t*)(g_h2l + (size_t)sl * NDIM + cbase);
#pragma unroll
                for (int nt = 0; nt < 8; ++nt) {
                    float v0 = acc[mt][nt][half * 2 + 0];
                    float v1 = acc[mt][nt][half * 2 + 1];
                    v0 = fmaxf(v0, 0.f); v0 *= v0;
                    v1 = fmaxf(v1, 0.f); v1 *= v1;
                    uint32_t hp = bfpack(v0, v1);
                    float r0 = v0 - __uint_as_float(hp << 16);
                    float r1 = v1 - __uint_as_float(hp & 0xffff0000u);
                    oh[nt * 4] = hp;
                    ol[nt * 4] = bfpack(r0, r1);
                }
            } else {
                float* oy = g_y + (size_t)sl * NDIM + cbase;
#pragma unroll
                for (int nt = 0; nt < 8; ++nt) {
                    *(float2*)(oy + nt * 8) =
                        make_float2(acc[mt][nt][half * 2 + 0], acc[mt][nt][half * 2 + 1]);
                }
            }
        }
    }
}

// ---------------------------------------------------------------------------
__global__ void k_combine(float* __restrict__ out, int out_size) {
    int t = blockIdx.x;
    int i = threadIdx.x;
    float w0 = g_w[2 * t];
    float w1 = g_w[2 * t + 1];
    float4 a = ((const float4*)(g_y + (size_t)(2 * t) * DIMSZ))[i];
    float4 b = ((const float4*)(g_y + (size_t)(2 * t + 1) * DIMSZ))[i];
    float4 r;
    r.x = w0 * a.x + w1 * b.x;
    r.y = w0 * a.y + w1 * b.y;
    r.z = w0 * a.z + w1 * b.z;
    r.w = w0 * a.w + w1 * b.w;
    ((float4*)(out + (size_t)t * DIMSZ))[i] = r;
    if (t == 0 && i == 0) {
        for (int j = TOK * DIMSZ; j < out_size; ++j) out[j] = 0.f;  // aux_loss tail
    }
}

// ---------------------------------------------------------------------------
extern "C" void kernel_launch(void* const* d_in, const int* in_sizes, int n_in,
                              void* d_out, int out_size) {
    const float* x   = (const float*)d_in[0];   // [1, 2048, 1024]
    const float* Wr  = (const float*)d_in[1];   // [8, 1024]
    const float* Wfc = (const float*)d_in[2];   // [8, 2048, 1024]
    const float* Wp  = (const float*)d_in[3];   // [8, 1024, 2048]
    float* out = (float*)d_out;

    cudaFuncSetAttribute(k_gemm_mma<DIMSZ, HID, true, 1, 1>,
                         cudaFuncAttributeMaxDynamicSharedMemorySize, GSMEM);
    cudaFuncSetAttribute(k_gemm_mma<HID, DIMSZ, false, 0, 2>,
                         cudaFuncAttributeMaxDynamicSharedMemorySize, GSMEM);

    k_zero_counts<<<1, 32>>>();
    k_router<<<TOK / 8, 256>>>(x, Wr);
    k_split<0><<<(TOK * DIMSZ / 4 + 255) / 256, 256>>>((const float4*)x, TOK * DIMSZ / 4);
    k_split<1><<<(NE * HID * DIMSZ / 4 + 255) / 256, 256>>>((const float4*)Wfc, NE * HID * DIMSZ / 4);
    k_split<2><<<(NE * DIMSZ * HID / 4 + 255) / 256, 256>>>((const float4*)Wp, NE * DIMSZ * HID / 4);
    // GEMM1: h2[slot, H] = relu(x[tok] @ Wfc[e]^T)^2  (bf16 hi/lo output)
    k_gemm_mma<DIMSZ, HID, true, 1, 1>
        <<<dim3(HID / 128, TOK / 128, NE), 128, GSMEM>>>();
    // GEMM2: y[slot, D] = h2[slot] @ Wp[e]^T
    k_gemm_mma<HID, DIMSZ, false, 0, 2>
        <<<dim3(DIMSZ / 128, TOK / 128, NE), 128, GSMEM>>>();
    k_combine<<<TOK, 256>>>(out, out_size);
}